// round 6
// baseline (speedup 1.0000x reference)
#include <cuda_runtime.h>
#include <cuda_fp16.h>
#include <cstdint>

// ============================================================================
// Problem dims
// ============================================================================
#define B_ROWS 2048
#define C_COLS 32000
#define DDIM   512
#define SCALE_F  32.0f
#define MARGIN_F 16.0f   // m * scale = 0.5 * 32

// GEMM tiling
#define BM 128
#define BN 256
#define KC 64                  // K elements per chunk (64 fp16 = 128B row = SW128 atom)
#define NCHUNK (DDIM / KC)     // 8
#define STAGES 3

#define A_TILE_B (BM * 128)    // 16384
#define W_TILE_B (BN * 128)    // 32768
#define STAGE_B  (A_TILE_B + W_TILE_B)   // 49152
#define SMEM_TOTAL (STAGES * STAGE_B)    // 147456

// ============================================================================
// Device scratch (allocation-free rule: __device__ globals)
// ============================================================================
__device__ __half g_A[(size_t)B_ROWS * DDIM];
__device__ __half g_W[(size_t)C_COLS * DDIM];

// ============================================================================
// PTX helpers (baseline sm_80/90 ISA only — no 'a'-gated features)
// ============================================================================
__device__ __forceinline__ uint32_t smem_u32(const void* p) {
    uint32_t a;
    asm("{ .reg .u64 t; cvta.to.shared.u64 t, %1; cvt.u32.u64 %0, t; }" : "=r"(a) : "l"(p));
    return a;
}

__device__ __forceinline__ void cp16(uint32_t smem_dst, const void* gmem_src) {
    asm volatile("cp.async.cg.shared.global [%0], [%1], 16;\n"
                 :: "r"(smem_dst), "l"(__cvta_generic_to_global(gmem_src)));
}
#define CP_COMMIT() asm volatile("cp.async.commit_group;\n" ::: "memory")

__device__ __forceinline__ uint32_t sw128(uint32_t off) {
    return off ^ ((off >> 3) & 0x70);
}

__device__ __forceinline__ void ldsm_x4(uint32_t (&r)[4], uint32_t addr) {
    asm volatile("ldmatrix.sync.aligned.m8n8.x4.shared.b16 {%0,%1,%2,%3}, [%4];"
                 : "=r"(r[0]), "=r"(r[1]), "=r"(r[2]), "=r"(r[3]) : "r"(addr));
}

__device__ __forceinline__ void mma16816(float (&d)[4], const uint32_t (&a)[4],
                                         uint32_t b0, uint32_t b1) {
    asm volatile("mma.sync.aligned.m16n8k16.row.col.f32.f16.f16.f32 "
                 "{%0,%1,%2,%3}, {%4,%5,%6,%7}, {%8,%9}, {%0,%1,%2,%3};"
                 : "+f"(d[0]), "+f"(d[1]), "+f"(d[2]), "+f"(d[3])
                 : "r"(a[0]), "r"(a[1]), "r"(a[2]), "r"(a[3]), "r"(b0), "r"(b1));
}

// ============================================================================
// Kernel 1: per-row L2 norm, convert to fp16.
// blockIdx.x in [0, B_ROWS + C_COLS); 128 threads, each handles one float4.
// ============================================================================
__global__ __launch_bounds__(128) void norm_kernel(
    const float* __restrict__ x, const float* __restrict__ w)
{
    int r = blockIdx.x;
    const float* src;
    __half* dst;
    size_t row;
    if (r < B_ROWS) { src = x; dst = g_A; row = (size_t)r; }
    else            { src = w; dst = g_W; row = (size_t)(r - B_ROWS); }

    int tid = threadIdx.x;
    float4 v = reinterpret_cast<const float4*>(src + row * DDIM)[tid];
    float s = v.x*v.x + v.y*v.y + v.z*v.z + v.w*v.w;
    #pragma unroll
    for (int o = 16; o; o >>= 1) s += __shfl_xor_sync(0xFFFFFFFFu, s, o);
    __shared__ float ws[4];
    if ((tid & 31) == 0) ws[tid >> 5] = s;
    __syncthreads();
    float tot = ws[0] + ws[1] + ws[2] + ws[3];
    float inv = 1.0f / fmaxf(sqrtf(tot), 1e-12f);

    __half h0 = __float2half_rn(v.x * inv);
    __half h1 = __float2half_rn(v.y * inv);
    __half h2 = __float2half_rn(v.z * inv);
    __half h3 = __float2half_rn(v.w * inv);
    uint2 pk;
    pk.x = (uint32_t)__half_as_ushort(h0) | ((uint32_t)__half_as_ushort(h1) << 16);
    pk.y = (uint32_t)__half_as_ushort(h2) | ((uint32_t)__half_as_ushort(h3) << 16);
    reinterpret_cast<uint2*>(dst + row * DDIM)[tid] = pk;
}

// ============================================================================
// Kernel 2: fp16 HMMA GEMM, CTA tile 128x256, 8 warps (2x4), warp tile 64x64,
// 3-stage cp.async pipeline, SW128 smem + ldmatrix.
// P = 32 * (A_norm . W_norm^T); written to both loss and predict halves.
// ============================================================================
__global__ __launch_bounds__(256, 1)
void gemm_kernel(float* __restrict__ outL, float* __restrict__ outP)
{
    extern __shared__ char smem[];
    const uint32_t base = smem_u32(smem);   // dynamic smem is 1024-aligned

    const int tid  = threadIdx.x;
    const int wid  = tid >> 5;
    const int lane = tid & 31;
    const int wm   = wid >> 2;              // 0..1  (M dim)
    const int wn   = wid & 3;               // 0..3  (N dim)
    const int m0   = blockIdx.x * BM;
    const int n0   = blockIdx.y * BN;

    // ---- chunk loader: A (128x64) + W (256x64) fp16 tiles into stage s -----
    auto load_chunk = [&](int ci, int s) {
        const uint32_t sbA = base + (uint32_t)s * STAGE_B;
        const uint32_t sbW = sbA + A_TILE_B;
        const int koff = ci * KC;
        #pragma unroll
        for (int t = 0; t < 4; t++) {               // A: 1024 16B units
            int idx = tid + t * 256;
            int row = idx >> 3, c = idx & 7;
            cp16(sbA + sw128((uint32_t)(row * 128 + c * 16)),
                 g_A + (size_t)(m0 + row) * DDIM + koff + c * 8);
        }
        #pragma unroll
        for (int t = 0; t < 8; t++) {               // W: 2048 16B units
            int idx = tid + t * 256;
            int row = idx >> 3, c = idx & 7;
            cp16(sbW + sw128((uint32_t)(row * 128 + c * 16)),
                 g_W + (size_t)(n0 + row) * DDIM + koff + c * 8);
        }
        CP_COMMIT();
    };

    // Prologue: fill the pipe
    load_chunk(0, 0);
    load_chunk(1, 1);
    load_chunk(2, 2);

    float acc[4][8][4];
    #pragma unroll
    for (int mt = 0; mt < 4; mt++)
        #pragma unroll
        for (int nt = 0; nt < 8; nt++)
            #pragma unroll
            for (int q = 0; q < 4; q++) acc[mt][nt][q] = 0.0f;

    // ldmatrix per-lane address components:
    //  A: lanes 0-15 -> rows 0-15 (k-unit = lane>>4) => frag regs in m16n8k16 order
    //  W: lanes 0-7 rows0-7 u0, 8-15 rows0-7 u1, 16-23 rows8-15 u0, 24-31 rows8-15 u1
    const uint32_t aRow  = (uint32_t)(wm * 64) + (lane & 15);       // + mt*16
    const uint32_t aHalf = (uint32_t)(lane >> 4);                   // 16B unit parity
    const uint32_t wRow  = (uint32_t)(wn * 64) + (lane & 7) + (((uint32_t)lane >> 4) << 3);
    const uint32_t wHalf = ((uint32_t)lane >> 3) & 1;

    for (int i = 0; i < NCHUNK; i++) {
        const int s = i % STAGES;
        if (i < NCHUNK - 2)      asm volatile("cp.async.wait_group 2;\n" ::: "memory");
        else if (i == NCHUNK - 2) asm volatile("cp.async.wait_group 1;\n" ::: "memory");
        else                     asm volatile("cp.async.wait_group 0;\n" ::: "memory");
        __syncthreads();

        const uint32_t sbA = base + (uint32_t)s * STAGE_B;
        const uint32_t sbW = sbA + A_TILE_B;

        #pragma unroll
        for (int kk = 0; kk < 4; kk++) {            // four k16 steps in Kc=64
            const uint32_t aU = (uint32_t)(kk * 2) + aHalf;
            const uint32_t bU = (uint32_t)(kk * 2) + wHalf;

            uint32_t a[4][4];
            #pragma unroll
            for (int mt = 0; mt < 4; mt++)
                ldsm_x4(a[mt], sbA + sw128((aRow + mt * 16) * 128 + aU * 16));

            uint32_t b[4][4];
            #pragma unroll
            for (int nt2 = 0; nt2 < 4; nt2++)
                ldsm_x4(b[nt2], sbW + sw128((wRow + nt2 * 16) * 128 + bU * 16));

            #pragma unroll
            for (int mt = 0; mt < 4; mt++)
                #pragma unroll
                for (int nt = 0; nt < 8; nt++)
                    mma16816(acc[mt][nt], a[mt],
                             b[nt >> 1][(nt & 1) * 2], b[nt >> 1][(nt & 1) * 2 + 1]);
        }

        __syncthreads();                            // all warps done reading stage s
        if (i + STAGES < NCHUNK) load_chunk(i + STAGES, s);
    }

    // ---- Epilogue: scale + direct STG (float2) to both output halves -------
    {
        const int rbase = m0 + wm * 64 + (lane >> 2);
        const int cbase = n0 + wn * 64 + (lane & 3) * 2;
        #pragma unroll
        for (int mt = 0; mt < 4; mt++) {
            #pragma unroll
            for (int nt = 0; nt < 8; nt++) {
                const int row = rbase + mt * 16;
                const int col = cbase + nt * 8;
                float2 v0 = make_float2(acc[mt][nt][0] * SCALE_F, acc[mt][nt][1] * SCALE_F);
                float2 v1 = make_float2(acc[mt][nt][2] * SCALE_F, acc[mt][nt][3] * SCALE_F);
                size_t o0 = (size_t)row * C_COLS + col;
                size_t o1 = (size_t)(row + 8) * C_COLS + col;
                *reinterpret_cast<float2*>(outL + o0) = v0;
                *reinterpret_cast<float2*>(outP + o0) = v0;
                *reinterpret_cast<float2*>(outL + o1) = v1;
                *reinterpret_cast<float2*>(outP + o1) = v1;
            }
        }
    }
}

// ============================================================================
// Kernel 3: margin scatter on the loss half.
// Targets may be int64 or int32 (jax canonicalization) — sniff layout:
// for int64 targets < 32000 every odd 32-bit word is 0; for 2048 random
// int32 targets the odds of the first 64 odd words all being zero are ~0.
// ============================================================================
__global__ void margin_kernel(const int* __restrict__ tgt, float* __restrict__ outL)
{
    bool is64 = true;
    #pragma unroll
    for (int j = 0; j < 64; j++)
        if (tgt[2 * j + 1] != 0) is64 = false;

    int b = blockIdx.x * blockDim.x + threadIdx.x;
    if (b < B_ROWS) {
        int t = is64 ? tgt[2 * b] : tgt[b];
        outL[(size_t)b * C_COLS + t] -= MARGIN_F;
    }
}

// ============================================================================
// Launch
// ============================================================================
extern "C" void kernel_launch(void* const* d_in, const int* in_sizes, int n_in,
                              void* d_out, int out_size)
{
    (void)in_sizes; (void)n_in; (void)out_size;
    const float* x   = (const float*)d_in[0];
    const float* w   = (const float*)d_in[1];
    const int*   tgt = (const int*)d_in[2];
    float* outL = (float*)d_out;
    float* outP = outL + (size_t)B_ROWS * C_COLS;

    norm_kernel<<<B_ROWS + C_COLS, 128>>>(x, w);

    cudaFuncSetAttribute(gemm_kernel, cudaFuncAttributeMaxDynamicSharedMemorySize, SMEM_TOTAL);
    gemm_kernel<<<dim3(B_ROWS / BM, C_COLS / BN, 1), 256, SMEM_TOTAL>>>(outL, outP);

    margin_kernel<<<B_ROWS / 256, 256>>>(tgt, outL);
}

// round 11
// speedup vs baseline: 1.0436x; 1.0436x over previous
#include <cuda_runtime.h>
#include <cuda_fp16.h>
#include <cstdint>

// ============================================================================
// Problem dims
// ============================================================================
#define B_ROWS 2048
#define C_COLS 32000
#define DDIM   512
#define SCALE_F  32.0f
#define MARGIN_F 16.0f   // m * scale = 0.5 * 32

// GEMM tiling
#define BM 128
#define BN 256
#define KC 64                  // K elements per chunk (64 fp16 = 128B row = SW128 atom)
#define NCHUNK (DDIM / KC)     // 8
#define STAGES 3

#define A_TILE_B (BM * 128)    // 16384
#define W_TILE_B (BN * 128)    // 32768
#define STAGE_B  (A_TILE_B + W_TILE_B)   // 49152
#define SMEM_TOTAL (STAGES * STAGE_B)    // 147456

// Epilogue smem staging: 128 rows x 264 floats (8-float pad vs bank conflicts)
#define EPL 264                           // floats per padded row
// 128 * 264 * 4 = 135168 <= SMEM_TOTAL   (reuses mainloop smem after drain)

// ============================================================================
// Device scratch (allocation-free rule: __device__ globals)
// ============================================================================
__device__ __half g_A[(size_t)B_ROWS * DDIM];
__device__ __half g_W[(size_t)C_COLS * DDIM];

// ============================================================================
// PTX helpers (baseline sm_80/90 ISA only — no 'a'-gated features)
// ============================================================================
__device__ __forceinline__ uint32_t smem_u32(const void* p) {
    uint32_t a;
    asm("{ .reg .u64 t; cvta.to.shared.u64 t, %1; cvt.u32.u64 %0, t; }" : "=r"(a) : "l"(p));
    return a;
}

__device__ __forceinline__ void cp16(uint32_t smem_dst, const void* gmem_src) {
    asm volatile("cp.async.cg.shared.global [%0], [%1], 16;\n"
                 :: "r"(smem_dst), "l"(__cvta_generic_to_global(gmem_src)));
}
#define CP_COMMIT() asm volatile("cp.async.commit_group;\n" ::: "memory")

__device__ __forceinline__ uint32_t sw128(uint32_t off) {
    return off ^ ((off >> 3) & 0x70);
}

__device__ __forceinline__ void ldsm_x4(uint32_t (&r)[4], uint32_t addr) {
    asm volatile("ldmatrix.sync.aligned.m8n8.x4.shared.b16 {%0,%1,%2,%3}, [%4];"
                 : "=r"(r[0]), "=r"(r[1]), "=r"(r[2]), "=r"(r[3]) : "r"(addr));
}

__device__ __forceinline__ void mma16816(float (&d)[4], const uint32_t (&a)[4],
                                         uint32_t b0, uint32_t b1) {
    asm volatile("mma.sync.aligned.m16n8k16.row.col.f32.f16.f16.f32 "
                 "{%0,%1,%2,%3}, {%4,%5,%6,%7}, {%8,%9}, {%0,%1,%2,%3};"
                 : "+f"(d[0]), "+f"(d[1]), "+f"(d[2]), "+f"(d[3])
                 : "r"(a[0]), "r"(a[1]), "r"(a[2]), "r"(a[3]), "r"(b0), "r"(b1));
}

// ============================================================================
// Kernel 1: per-row L2 norm + fp16 convert. Warp-per-row, no block syncs.
// grid = (B_ROWS + C_COLS) / 8 blocks of 256 threads (8 warps = 8 rows).
// ============================================================================
__global__ __launch_bounds__(256) void norm_kernel(
    const float* __restrict__ x, const float* __restrict__ w)
{
    int gw = blockIdx.x * 8 + (threadIdx.x >> 5);   // global warp id = row id
    int lane = threadIdx.x & 31;

    const float* src;
    __half* dst;
    size_t row;
    if (gw < B_ROWS) { src = x; dst = g_A; row = (size_t)gw; }
    else             { src = w; dst = g_W; row = (size_t)(gw - B_ROWS); }

    const float4* p = reinterpret_cast<const float4*>(src + row * DDIM);
    float4 v[4];
    float s = 0.0f;
    #pragma unroll
    for (int i = 0; i < 4; i++) {
        v[i] = p[lane + 32 * i];
        s += v[i].x*v[i].x + v[i].y*v[i].y + v[i].z*v[i].z + v[i].w*v[i].w;
    }
    #pragma unroll
    for (int o = 16; o; o >>= 1) s += __shfl_xor_sync(0xFFFFFFFFu, s, o);
    float inv = 1.0f / fmaxf(sqrtf(s), 1e-12f);

    uint2* dp = reinterpret_cast<uint2*>(dst + row * DDIM);
    #pragma unroll
    for (int i = 0; i < 4; i++) {
        __half h0 = __float2half_rn(v[i].x * inv);
        __half h1 = __float2half_rn(v[i].y * inv);
        __half h2 = __float2half_rn(v[i].z * inv);
        __half h3 = __float2half_rn(v[i].w * inv);
        uint2 pk;
        pk.x = (uint32_t)__half_as_ushort(h0) | ((uint32_t)__half_as_ushort(h1) << 16);
        pk.y = (uint32_t)__half_as_ushort(h2) | ((uint32_t)__half_as_ushort(h3) << 16);
        dp[lane + 32 * i] = pk;
    }
}

// ============================================================================
// Kernel 2: fp16 HMMA GEMM, CTA tile 128x256, 8 warps (2x4), warp tile 64x64,
// 3-stage cp.async pipeline, SW128 smem + ldmatrix.
// Epilogue stages the fp32 tile through smem for fully-coalesced STG.128.
// P = 32 * (A_norm . W_norm^T); written to both loss and predict halves.
// ============================================================================
__global__ __launch_bounds__(256, 1)
void gemm_kernel(float* __restrict__ outL, float* __restrict__ outP)
{
    extern __shared__ char smem[];
    const uint32_t base = smem_u32(smem);   // dynamic smem is 1024-aligned

    const int tid  = threadIdx.x;
    const int wid  = tid >> 5;
    const int lane = tid & 31;
    const int wm   = wid >> 2;              // 0..1  (M dim)
    const int wn   = wid & 3;               // 0..3  (N dim)
    const int m0   = blockIdx.x * BM;
    const int n0   = blockIdx.y * BN;

    // ---- chunk loader: A (128x64) + W (256x64) fp16 tiles into stage s -----
    auto load_chunk = [&](int ci, int s) {
        const uint32_t sbA = base + (uint32_t)s * STAGE_B;
        const uint32_t sbW = sbA + A_TILE_B;
        const int koff = ci * KC;
        #pragma unroll
        for (int t = 0; t < 4; t++) {               // A: 1024 16B units
            int idx = tid + t * 256;
            int row = idx >> 3, c = idx & 7;
            cp16(sbA + sw128((uint32_t)(row * 128 + c * 16)),
                 g_A + (size_t)(m0 + row) * DDIM + koff + c * 8);
        }
        #pragma unroll
        for (int t = 0; t < 8; t++) {               // W: 2048 16B units
            int idx = tid + t * 256;
            int row = idx >> 3, c = idx & 7;
            cp16(sbW + sw128((uint32_t)(row * 128 + c * 16)),
                 g_W + (size_t)(n0 + row) * DDIM + koff + c * 8);
        }
        CP_COMMIT();
    };

    // Prologue: fill the pipe
    load_chunk(0, 0);
    load_chunk(1, 1);
    load_chunk(2, 2);

    float acc[4][8][4];
    #pragma unroll
    for (int mt = 0; mt < 4; mt++)
        #pragma unroll
        for (int nt = 0; nt < 8; nt++)
            #pragma unroll
            for (int q = 0; q < 4; q++) acc[mt][nt][q] = 0.0f;

    // ldmatrix per-lane address components:
    //  A: lanes 0-15 -> rows 0-15 (k-unit = lane>>4) => frag regs in m16n8k16 order
    //  W: lanes 0-7 rows0-7 u0, 8-15 rows0-7 u1, 16-23 rows8-15 u0, 24-31 rows8-15 u1
    const uint32_t aRow  = (uint32_t)(wm * 64) + (lane & 15);       // + mt*16
    const uint32_t aHalf = (uint32_t)(lane >> 4);                   // 16B unit parity
    const uint32_t wRow  = (uint32_t)(wn * 64) + (lane & 7) + (((uint32_t)lane >> 4) << 3);
    const uint32_t wHalf = ((uint32_t)lane >> 3) & 1;

    for (int i = 0; i < NCHUNK; i++) {
        const int s = i % STAGES;
        if (i < NCHUNK - 2)       asm volatile("cp.async.wait_group 2;\n" ::: "memory");
        else if (i == NCHUNK - 2) asm volatile("cp.async.wait_group 1;\n" ::: "memory");
        else                      asm volatile("cp.async.wait_group 0;\n" ::: "memory");
        __syncthreads();

        const uint32_t sbA = base + (uint32_t)s * STAGE_B;
        const uint32_t sbW = sbA + A_TILE_B;

        #pragma unroll
        for (int kk = 0; kk < 4; kk++) {            // four k16 steps in Kc=64
            const uint32_t aU = (uint32_t)(kk * 2) + aHalf;
            const uint32_t bU = (uint32_t)(kk * 2) + wHalf;

            uint32_t a[4][4];
            #pragma unroll
            for (int mt = 0; mt < 4; mt++)
                ldsm_x4(a[mt], sbA + sw128((aRow + mt * 16) * 128 + aU * 16));

            uint32_t b[4][4];
            #pragma unroll
            for (int nt2 = 0; nt2 < 4; nt2++)
                ldsm_x4(b[nt2], sbW + sw128((wRow + nt2 * 16) * 128 + bU * 16));

            #pragma unroll
            for (int mt = 0; mt < 4; mt++)
                #pragma unroll
                for (int nt = 0; nt < 8; nt++)
                    mma16816(acc[mt][nt], a[mt],
                             b[nt >> 1][(nt & 1) * 2], b[nt >> 1][(nt & 1) * 2 + 1]);
        }

        __syncthreads();                            // all warps done reading stage s
        if (i + STAGES < NCHUNK) load_chunk(i + STAGES, s);
    }

    // ---- Epilogue: acc -> smem (scaled) -> fully-coalesced STG.128 x2 ------
    __syncthreads();                                // mainloop smem now reusable
    {
        float* ep = reinterpret_cast<float*>(smem);
        // STS phase: each warp writes its 64x64 warp tile
        const int r0 = wm * 64 + (lane >> 2);       // + mt*16 (+8 for upper half)
        const int c0 = wn * 64 + (lane & 3) * 2;    // + nt*8
        #pragma unroll
        for (int mt = 0; mt < 4; mt++) {
            float* rpL = ep + (r0 + mt * 16) * EPL + c0;
            float* rpH = rpL + 8 * EPL;
            #pragma unroll
            for (int nt = 0; nt < 8; nt++) {
                *reinterpret_cast<float2*>(rpL + nt * 8) =
                    make_float2(acc[mt][nt][0] * SCALE_F, acc[mt][nt][1] * SCALE_F);
                *reinterpret_cast<float2*>(rpH + nt * 8) =
                    make_float2(acc[mt][nt][2] * SCALE_F, acc[mt][nt][3] * SCALE_F);
            }
        }
        __syncthreads();

        // Store phase: 256 threads cover 4 rows x 64 float4 per pass, 32 passes.
        const int pr = tid >> 6;                    // 0..3 row-in-pass
        const int c4 = tid & 63;                    // float4 column index
        #pragma unroll 4
        for (int pass = 0; pass < 32; pass++) {
            const int r = pass * 4 + pr;
            float4 v = *reinterpret_cast<const float4*>(ep + r * EPL + c4 * 4);
            size_t o = (size_t)(m0 + r) * C_COLS + (size_t)(n0 + c4 * 4);
            *reinterpret_cast<float4*>(outL + o) = v;
            *reinterpret_cast<float4*>(outP + o) = v;
        }
    }
}

// ============================================================================
// Kernel 3: margin scatter on the loss half.
// Targets may be int64 or int32 (jax canonicalization) — sniff layout:
// for int64 targets < 32000 every odd 32-bit word is 0; for 2048 random
// int32 targets the odds of the first 64 odd words all being zero are ~0.
// ============================================================================
__global__ void margin_kernel(const int* __restrict__ tgt, float* __restrict__ outL)
{
    bool is64 = true;
    #pragma unroll
    for (int j = 0; j < 64; j++)
        if (tgt[2 * j + 1] != 0) is64 = false;

    int b = blockIdx.x * blockDim.x + threadIdx.x;
    if (b < B_ROWS) {
        int t = is64 ? tgt[2 * b] : tgt[b];
        outL[(size_t)b * C_COLS + t] -= MARGIN_F;
    }
}

// ============================================================================
// Launch
// ============================================================================
extern "C" void kernel_launch(void* const* d_in, const int* in_sizes, int n_in,
                              void* d_out, int out_size)
{
    (void)in_sizes; (void)n_in; (void)out_size;
    const float* x   = (const float*)d_in[0];
    const float* w   = (const float*)d_in[1];
    const int*   tgt = (const int*)d_in[2];
    float* outL = (float*)d_out;
    float* outP = outL + (size_t)B_ROWS * C_COLS;

    norm_kernel<<<(B_ROWS + C_COLS) / 8, 256>>>(x, w);

    cudaFuncSetAttribute(gemm_kernel, cudaFuncAttributeMaxDynamicSharedMemorySize, SMEM_TOTAL);
    gemm_kernel<<<dim3(B_ROWS / BM, C_COLS / BN, 1), 256, SMEM_TOTAL>>>(outL, outP);

    margin_kernel<<<B_ROWS / 256, 256>>>(tgt, outL);
}